// round 2
// baseline (speedup 1.0000x reference)
#include <cuda_runtime.h>
#include <math.h>

#define NB_ 16
#define NC 64
#define NH 130
#define NKX 66
#define NM 12
#define NE 15
#define NR 4
#define HW (NH*NH)          /* 16900 */
#define ZSZ (NH*NKX)        /* 8580 */
#define BC (NB_*NC)         /* 1024 */

/* ---------------- scratch (device globals, no runtime allocation) -------- */
__device__ float  g_hA[BC*HW];
__device__ float  g_hB[BC*HW];
__device__ float2 g_Zx[BC*ZSZ];
__device__ float2 g_Modes[BC*24*NM];
__device__ float2 g_OutModes[BC*24*NM];
__device__ float2 g_Ty[BC*NH*NM];
__device__ float  g_sab[BC];
__device__ float  g_gate[NB_*NE];
__device__ float2 g_M1[NE*NC*NC];
__device__ float2 g_M2[NE*NC*NC];
__device__ float2 g_d1[NB_*NC*NC];
__device__ float2 g_d2[NB_*NC*NC];
__device__ float2 g_tw[NH];

__device__ __forceinline__ float gelu_exact(float v){
    return 0.5f*v*(1.f+erff(v*0.70710678118654752f));
}

/* twiddle table: tw[k] = (cos, sin)(2*pi*k/130) */
__global__ void ktw(){
    int k = threadIdx.x;
    if(k < NH){
        double th = 6.283185307179586476925286766559 * (double)k / 130.0;
        g_tw[k] = make_float2((float)cos(th), (float)sin(th));
    }
}

/* lift: h0[b,c,y,x] = concat(x,grid)@fc0_w + fc0_b ; zero pad region */
__global__ void k0(const float* __restrict__ xin, const float* __restrict__ grd,
                   const float* __restrict__ w, const float* __restrict__ bias){
    int y = blockIdx.x, b = blockIdx.y, tid = threadIdx.x;
    __shared__ float in[128*12];
    __shared__ float ws[12*NC];
    __shared__ float bs[NC];
    for(int i=tid;i<12*NC;i+=256) ws[i]=w[i];
    if(tid<NC) bs[tid]=bias[tid];
    if(y<128){
        for(int i=tid;i<128*10;i+=256){ int xx=i/10,t=i%10; in[xx*12+t]=xin[(((size_t)b*128+y)*128+xx)*10+t]; }
        for(int i=tid;i<128*2 ;i+=256){ int xx=i/2 ,t=i%2 ; in[xx*12+10+t]=grd[(((size_t)b*128+y)*128+xx)*2+t]; }
    }
    __syncthreads();
    for(int idx=tid; idx<NC*NH; idx+=256){
        int c=idx/NH, xx=idx%NH;
        float v=0.f;
        if(y<128 && xx<128){
            v=bs[c];
            #pragma unroll
            for(int t=0;t<12;t++) v += in[xx*12+t]*ws[t*NC+c];
        }
        g_hA[(((size_t)b*NC+c)*NH+y)*NH+xx]=v;
    }
}

/* K1: rfft along x for each (b,c): Zx[y,kx] = sum_x h[y,x] e^{-2pi i kx x /130} */
__global__ void __launch_bounds__(576) k1(int curA){
    extern __shared__ unsigned char s_raw[];
    float*  hs  = (float*)s_raw;                 /* 132*130 floats (padded) */
    float2* tws = (float2*)(hs + 132*NH);        /* 130 */
    const float* hin = curA ? g_hA : g_hB;
    int bc = blockIdx.x, tid = threadIdx.x;
    const float* hp = hin + (size_t)bc*HW;
    for(int i=tid;i<HW;i+=576) hs[i]=hp[i];
    for(int i=HW+tid;i<132*NH;i+=576) hs[i]=0.f;
    for(int i=tid;i<NH;i+=576) tws[i]=g_tw[i];
    __syncthreads();
    if(tid < 561){
        int ty = tid/17, tk = tid%17;
        int y0 = ty*4, k0 = tk*4;
        float sr[4][4], si[4][4];
        #pragma unroll
        for(int a=0;a<4;a++)
            #pragma unroll
            for(int j=0;j<4;j++){ sr[a][j]=0.f; si[a][j]=0.f; }
        int idx[4];
        #pragma unroll
        for(int j=0;j<4;j++) idx[j]=0;
        for(int x=0;x<NH;x++){
            float hv[4];
            #pragma unroll
            for(int a=0;a<4;a++) hv[a]=hs[(y0+a)*NH+x];
            #pragma unroll
            for(int j=0;j<4;j++){
                float2 w = tws[idx[j]];
                #pragma unroll
                for(int a=0;a<4;a++){
                    sr[a][j] += hv[a]*w.x;
                    si[a][j] += hv[a]*w.y;
                }
                idx[j]+=k0+j; if(idx[j]>=NH) idx[j]-=NH;
            }
        }
        float2* zp = g_Zx + (size_t)bc*ZSZ;
        #pragma unroll
        for(int a=0;a<4;a++){
            int y=y0+a; if(y>=NH) break;
            #pragma unroll
            for(int j=0;j<4;j++){
                int k=k0+j;
                if(k<NKX) zp[y*NKX+k]=make_float2(sr[a][j],-si[a][j]);
            }
        }
    }
}

/* K2: full 130-pt DFT along y, fused |F| reduction (gate) + mode extraction */
__global__ void __launch_bounds__(576) k2(){
    extern __shared__ unsigned char s_raw[];
    float2* zs  = (float2*)s_raw;           /* 8584 (padded) */
    float2* tws = zs + 8584;                /* 130 */
    float*  red = (float*)(tws + NH);       /* 576 */
    int bc = blockIdx.x, tid = threadIdx.x;
    const float2* zp = g_Zx + (size_t)bc*ZSZ;
    for(int i=tid;i<ZSZ;i+=576) zs[i]=zp[i];
    for(int i=ZSZ+tid;i<8584;i+=576) zs[i]=make_float2(0.f,0.f);
    for(int i=tid;i<NH;i+=576) tws[i]=g_tw[i];
    __syncthreads();
    float lsum=0.f;
    if(tid < 561){
        int tky=tid/17, tkx=tid%17;
        int ky0=tky*4, kx0=tkx*4;
        float fr[4][4], fi[4][4];
        #pragma unroll
        for(int j=0;j<4;j++)
            #pragma unroll
            for(int t=0;t<4;t++){ fr[j][t]=0.f; fi[j][t]=0.f; }
        int idx[4], stp[4];
        #pragma unroll
        for(int j=0;j<4;j++){ int ky=ky0+j; stp[j]=(ky>=NH)?ky-NH:ky; idx[j]=0; }
        for(int y=0;y<NH;y++){
            float2 zv[4];
            #pragma unroll
            for(int t=0;t<4;t++) zv[t]=zs[y*NKX + kx0 + t];
            #pragma unroll
            for(int j=0;j<4;j++){
                float2 w = tws[idx[j]];
                #pragma unroll
                for(int t=0;t<4;t++){
                    fr[j][t] += zv[t].x*w.x + zv[t].y*w.y;
                    fi[j][t] += zv[t].y*w.x - zv[t].x*w.y;
                }
                idx[j]+=stp[j]; if(idx[j]>=NH) idx[j]-=NH;
            }
        }
        #pragma unroll
        for(int j=0;j<4;j++){
            int ky=ky0+j; if(ky>=NH) break;
            #pragma unroll
            for(int t=0;t<4;t++){
                int kx=kx0+t; if(kx>=NKX) continue;
                float re=fr[j][t], im=fi[j][t];
                lsum += sqrtf(re*re+im*im);
                if(kx<NM && (ky<NM || ky>=NH-NM)){
                    int jr = (ky<NM)? ky : ky-106;
                    g_Modes[((size_t)bc*24+jr)*NM+kx]=make_float2(re,im);
                }
            }
        }
    }
    red[tid]=lsum; __syncthreads();
    if(tid<64) red[tid]+=red[tid+512];
    __syncthreads();
    for(int s=256;s>0;s>>=1){ if(tid<s) red[tid]+=red[tid+s]; __syncthreads(); }
    if(tid==0) g_sab[bc]=red[0]/8580.f;
}

/* gate: softmax(sab @ gw + gb) */
__global__ void kgate(const float* __restrict__ gw, const float* __restrict__ gb){
    int b=blockIdx.x, e=threadIdx.x;
    __shared__ float lg[NE];
    if(e<NE){
        float s=gb[e];
        for(int c=0;c<NC;c++) s += g_sab[b*NC+c]*gw[c*NE+e];
        lg[e]=s;
    }
    __syncthreads();
    if(e==0){
        float mx=-1e30f;
        for(int i=0;i<NE;i++) mx=fmaxf(mx,lg[i]);
        float den=0.f;
        for(int i=0;i<NE;i++){ lg[i]=expf(lg[i]-mx); den+=lg[i]; }
        for(int i=0;i<NE;i++) g_gate[b*NE+i]=lg[i]/den;
    }
}

/* M[e] = A[e] @ B[e]  (complex low-rank products, layer weights) */
__global__ void km(const float* __restrict__ A1,const float* __restrict__ B1,
                   const float* __restrict__ A2,const float* __restrict__ B2){
    int e=blockIdx.x, which=blockIdx.y;
    const float* A  = which? A2:A1;
    const float* Bm = which? B2:B1;
    float2* Mo = which? g_M2:g_M1;
    __shared__ float2 as[NC*NR], bs[NR*NC];
    for(int i=threadIdx.x;i<NC*NR;i+=blockDim.x){
        as[i]=make_float2(A [(e*NC*NR+i)*2], A [(e*NC*NR+i)*2+1]);
        bs[i]=make_float2(Bm[(e*NR*NC+i)*2], Bm[(e*NR*NC+i)*2+1]);
    }
    __syncthreads();
    for(int idx=threadIdx.x; idx<NC*NC; idx+=blockDim.x){
        int i=idx/NC, o=idx%NC;
        float rr=0.f, ri=0.f;
        #pragma unroll
        for(int r=0;r<NR;r++){
            float2 a=as[i*NR+r], b2=bs[r*NC+o];
            rr += a.x*b2.x - a.y*b2.y;
            ri += a.x*b2.y + a.y*b2.x;
        }
        Mo[e*NC*NC+idx]=make_float2(rr,ri);
    }
}

/* d[b] = 0.1 * sum_e g[b,e] M[e] */
__global__ void kd(){
    int b=blockIdx.x, which=blockIdx.y;
    const float2* Mm = which? g_M2 : g_M1;
    float2* dd = which? g_d2 : g_d1;
    __shared__ float gs[NE];
    if(threadIdx.x<NE) gs[threadIdx.x]=g_gate[b*NE+threadIdx.x];
    __syncthreads();
    for(int idx=threadIdx.x; idx<NC*NC; idx+=blockDim.x){
        float rr=0.f, ri=0.f;
        #pragma unroll
        for(int e=0;e<NE;e++){
            float2 m=Mm[e*NC*NC+idx];
            rr += gs[e]*m.x; ri += gs[e]*m.y;
        }
        dd[b*NC*NC+idx]=make_float2(0.1f*rr,0.1f*ri);
    }
}

/* mode mixing: o[b,o,p,q] = sum_i ft[b,i,p,q] * (W[i,o,p,q] + d[b,i,o]) */
__global__ void kmix(const float* __restrict__ W1,const float* __restrict__ W2){
    extern __shared__ unsigned char s_raw[];
    float2* tops = (float2*)s_raw;       /* 64*144 */
    float2* ds   = tops + NC*144;        /* 64*8 */
    int ot=blockIdx.x, half=blockIdx.y, b=blockIdx.z;
    const float2* W    = (const float2*)(half? W2:W1);
    const float2* dmat = half? g_d2 : g_d1;
    int jbase = half*NM;
    for(int i=threadIdx.x;i<NC*144;i+=256){
        int c=i/144, pq=i%144;
        tops[i]=g_Modes[(((size_t)b*NC+c)*24 + jbase + pq/NM)*NM + pq%NM];
    }
    for(int i=threadIdx.x;i<NC*8;i+=256){
        int c=i/8, oo=i%8;
        ds[i]=dmat[((size_t)b*NC+c)*NC + ot*8+oo];
    }
    __syncthreads();
    for(int idx=threadIdx.x; idx<8*144; idx+=256){
        int oo=idx/144, pq=idx%144; int o=ot*8+oo;
        float rr=0.f, ri=0.f;
        #pragma unroll 8
        for(int i=0;i<NC;i++){
            float2 t=tops[i*144+pq];
            float2 d=ds[i*8+oo];
            float2 w=W[((size_t)i*NC+o)*144+pq];
            float wr=w.x+d.x, wi=w.y+d.y;
            rr += t.x*wr - t.y*wi;
            ri += t.x*wi + t.y*wr;
        }
        g_OutModes[(((size_t)b*NC+o)*24 + jbase + pq/NM)*NM + pq%NM]=make_float2(rr,ri);
    }
}

/* inverse fft along y (only 24 nonzero bins): Ty[y,q] */
__global__ void kinv1(){
    __shared__ float2 om[24*NM];
    __shared__ float2 tws[NH];
    int bc=blockIdx.x, tid=threadIdx.x;
    for(int i=tid;i<24*NM;i+=blockDim.x) om[i]=g_OutModes[(size_t)bc*24*NM+i];
    for(int i=tid;i<NH;i+=blockDim.x) tws[i]=g_tw[i];
    __syncthreads();
    for(int idx=tid; idx<NH*NM; idx+=blockDim.x){
        int y=idx/NM, q=idx%NM;
        float rr=0.f, ri=0.f;
        #pragma unroll
        for(int j=0;j<24;j++){
            int ky = (j<NM)? j : j+106;
            int t = (ky*y)%NH;
            float2 w=tws[t];
            float2 o=om[j*NM+q];
            rr += o.x*w.x - o.y*w.y;
            ri += o.x*w.y + o.y*w.x;
        }
        g_Ty[(size_t)bc*NH*NM+idx]=make_float2(rr*(1.f/130.f), ri*(1.f/130.f));
    }
}

/* fused: irfft along x (12 bins) + pointwise conv + bias + (gelu) -> new h */
__global__ void kfinal(int curA, const float* __restrict__ cw,
                       const float* __restrict__ cb, int dogelu){
    extern __shared__ unsigned char s_raw[];
    float*  hs  = (float*)s_raw;           /* 64*130 */
    float*  cws = hs + NC*NH;              /* 4096 */
    float*  cbs = cws + NC*NC;             /* 64 */
    float2* tys = (float2*)(cbs + NC);     /* 64*12 */
    float2* tws = tys + NC*NM;             /* 130 */
    const float* hin  = curA ? g_hA : g_hB;
    float*       hout = curA ? g_hB : g_hA;
    int y=blockIdx.x, b=blockIdx.y, tid=threadIdx.x;
    for(int i=tid;i<NC*NH;i+=256){ int c=i/NH,x=i%NH; hs[i]=hin[(((size_t)b*NC+c)*NH+y)*NH+x]; }
    for(int i=tid;i<NC*NC;i+=256) cws[i]=cw[i];
    if(tid<NC) cbs[tid]=cb[tid];
    for(int i=tid;i<NC*NM;i+=256){ int c=i/NM,q=i%NM; tys[i]=g_Ty[((size_t)(b*NC+c)*NH+y)*NM+q]; }
    for(int i=tid;i<NH;i+=256) tws[i]=g_tw[i];
    __syncthreads();
    for(int idx=tid; idx<NC*NH; idx+=256){
        int o=idx/NH, x=idx%NH;
        float2 t0=tys[o*NM];
        float sacc = t0.x;
        int id=0;
        #pragma unroll
        for(int q=1;q<NM;q++){
            id+=x; if(id>=NH) id-=NH;
            float2 t=tys[o*NM+q]; float2 w=tws[id];
            sacc += 2.f*(t.x*w.x - t.y*w.y);
        }
        sacc *= (1.f/130.f);
        float cacc = cbs[o];
        #pragma unroll 16
        for(int i=0;i<NC;i++) cacc += cws[o*NC+i]*hs[i*NH+x];
        float v = sacc + cacc;
        if(dogelu) v = gelu_exact(v);
        hout[(((size_t)b*NC+o)*NH+y)*NH+x]=v;
    }
}

/* head: crop + fc1 + gelu + fc2 */
__global__ void __launch_bounds__(128) kout(const float* __restrict__ f1w,
        const float* __restrict__ f1b, const float* __restrict__ f2w,
        const float* __restrict__ f2b, float* __restrict__ out){
    extern __shared__ unsigned char s_raw[];
    float* hs  = (float*)s_raw;     /* 64*128 */
    float* w1s = hs + 8192;         /* 8192 */
    float* b1s = w1s + 8192;        /* 128 */
    float* w2s = b1s + 128;         /* 128 */
    int y=blockIdx.x, b=blockIdx.y, tid=threadIdx.x;
    for(int i=tid;i<8192;i+=128){ int c=i/128,x=i%128; hs[i]=g_hA[(((size_t)b*NC+c)*NH+y)*NH+x]; }
    for(int i=tid;i<8192;i+=128) w1s[i]=f1w[i];
    if(tid<128){ b1s[tid]=f1b[tid]; w2s[tid]=f2w[tid]; }
    __syncthreads();
    int x=tid;
    float v[NC];
    #pragma unroll
    for(int i=0;i<NC;i++) v[i]=hs[i*128+x];
    float acc=f2b[0];
    for(int j=0;j<128;j++){
        float s=b1s[j];
        #pragma unroll
        for(int i=0;i<NC;i++) s += v[i]*w1s[i*128+j];
        acc += gelu_exact(s)*w2s[j];
    }
    out[((size_t)(b*128+y))*128+x]=acc;
}

/* ------------------------------- host ------------------------------------ */
extern "C" void kernel_launch(void* const* d_in, const int* in_sizes, int n_in,
                              void* d_out, int out_size){
    const float* x    =(const float*)d_in[0];
    const float* grd  =(const float*)d_in[1];
    const float* fc0w =(const float*)d_in[2];
    const float* fc0b =(const float*)d_in[3];
    const float* W1   =(const float*)d_in[4];
    const float* W2   =(const float*)d_in[5];
    const float* A1   =(const float*)d_in[6];
    const float* B1   =(const float*)d_in[7];
    const float* A2   =(const float*)d_in[8];
    const float* B2   =(const float*)d_in[9];
    const float* gw   =(const float*)d_in[10];
    const float* gb   =(const float*)d_in[11];
    const float* cw   =(const float*)d_in[12];
    const float* cb   =(const float*)d_in[13];
    const float* f1w  =(const float*)d_in[14];
    const float* f1b  =(const float*)d_in[15];
    const float* f2w  =(const float*)d_in[16];
    const float* f2b  =(const float*)d_in[17];
    float* out=(float*)d_out;

    const int SM1   = 132*NH*4 + NH*8;                 /* 69680 */
    const int SM2   = 8584*8 + NH*8 + 576*4;           /* 72016 */
    const int SMMIX = NC*144*8 + NC*8*8;               /* 77824 */
    const int SMF   = (NC*NH + NC*NC + NC)*4 + (NC*NM + NH)*8; /* 57104 */
    const int SMO   = (8192+8192+128+128)*4;           /* 66560 */

    cudaFuncSetAttribute(k1,     cudaFuncAttributeMaxDynamicSharedMemorySize, SM1);
    cudaFuncSetAttribute(k2,     cudaFuncAttributeMaxDynamicSharedMemorySize, SM2);
    cudaFuncSetAttribute(kmix,   cudaFuncAttributeMaxDynamicSharedMemorySize, SMMIX);
    cudaFuncSetAttribute(kfinal, cudaFuncAttributeMaxDynamicSharedMemorySize, SMF);
    cudaFuncSetAttribute(kout,   cudaFuncAttributeMaxDynamicSharedMemorySize, SMO);

    ktw<<<1,160>>>();
    k0<<<dim3(NH,NB_),256>>>(x,grd,fc0w,fc0b);

    for(int l=0;l<4;l++){
        int curA = (l%2==0) ? 1 : 0;
        k1<<<BC,576,SM1>>>(curA);
        k2<<<BC,576,SM2>>>();
        kgate<<<NB_,32>>>(gw + (size_t)l*NC*NE, gb + (size_t)l*NE);
        km<<<dim3(NE,2),256>>>(A1+(size_t)l*NE*NC*NR*2, B1+(size_t)l*NE*NR*NC*2,
                               A2+(size_t)l*NE*NC*NR*2, B2+(size_t)l*NE*NR*NC*2);
        kd<<<dim3(NB_,2),256>>>();
        kmix<<<dim3(8,2,NB_),256,SMMIX>>>(W1+(size_t)l*NC*NC*NM*NM*2,
                                          W2+(size_t)l*NC*NC*NM*NM*2);
        kinv1<<<BC,512>>>();
        kfinal<<<dim3(NH,NB_),256,SMF>>>(curA, cw+(size_t)l*NC*NC,
                                         cb+(size_t)l*NC, (l<3)?1:0);
    }
    kout<<<dim3(128,NB_),128,SMO>>>(f1w,f1b,f2w,f2b,out);
}

// round 4
// speedup vs baseline: 1.5350x; 1.5350x over previous
#include <cuda_runtime.h>
#include <math.h>

#define NB_ 16
#define NC 64
#define NH 130
#define NKX 66
#define NM 12
#define NE 15
#define NR 4
#define HW (NH*NH)          /* 16900 */
#define BC (NB_*NC)         /* 1024 */

/* ---------------- scratch (device globals, no runtime allocation) -------- */
__device__ float  g_hA[BC*HW];
__device__ float  g_hB[BC*HW];
__device__ float2 g_Modes[BC*24*NM];
__device__ float2 g_OutModes[BC*24*NM];
__device__ float2 g_Ty[BC*NH*NM];
__device__ float  g_sab[BC];
__device__ float  g_gate[NB_*NE];
__device__ float2 g_M1[NE*NC*NC];
__device__ float2 g_M2[NE*NC*NC];
__device__ float2 g_d1[NB_*NC*NC];
__device__ float2 g_d2[NB_*NC*NC];
__device__ float2 g_tw[NH];

__device__ __forceinline__ float gelu_exact(float v){
    return 0.5f*v*(1.f+erff(v*0.70710678118654752f));
}

/* twiddle table: tw[k] = (cos, sin)(2*pi*k/130) */
__global__ void ktw(){
    int k = threadIdx.x;
    if(k < NH){
        double th = 6.283185307179586476925286766559 * (double)k / 130.0;
        g_tw[k] = make_float2((float)cos(th), (float)sin(th));
    }
}

/* lift: h0[b,c,y,x] = concat(x,grid)@fc0_w + fc0_b ; zero pad region */
__global__ void k0(const float* __restrict__ xin, const float* __restrict__ grd,
                   const float* __restrict__ w, const float* __restrict__ bias){
    int y = blockIdx.x, b = blockIdx.y, tid = threadIdx.x;
    __shared__ float in[128*12];
    __shared__ float ws[12*NC];
    __shared__ float bs[NC];
    for(int i=tid;i<12*NC;i+=256) ws[i]=w[i];
    if(tid<NC) bs[tid]=bias[tid];
    if(y<128){
        for(int i=tid;i<128*10;i+=256){ int xx=i/10,t=i%10; in[xx*12+t]=xin[(((size_t)b*128+y)*128+xx)*10+t]; }
        for(int i=tid;i<128*2 ;i+=256){ int xx=i/2 ,t=i%2 ; in[xx*12+10+t]=grd[(((size_t)b*128+y)*128+xx)*2+t]; }
    }
    __syncthreads();
    for(int idx=tid; idx<NC*NH; idx+=256){
        int c=idx/NH, xx=idx%NH;
        float v=0.f;
        if(y<128 && xx<128){
            v=bs[c];
            #pragma unroll
            for(int t=0;t<12;t++) v += in[xx*12+t]*ws[t*NC+c];
        }
        g_hA[(((size_t)b*NC+c)*NH+y)*NH+xx]=v;
    }
}

/* ===================== fused mixed-radix 2D forward FFT ====================
 * 130 = 13*10.  Per (b,c) block:
 *  stage A: x-radix-10   GA[y][q][r]   = sum_p h[y][13p+q] e^{-2pi i r p/10}
 *           (h real => GA[10-r] = conj(GA[r]); store only r=0..5)
 *  stage B: x-finish     Z[y][kx]      = sum_q e^{-2pi i kx q/130} GA[y][q][kx%10]
 *  stage C: y-radix-10   GC[r][q2][kx] = sum_p Z[13p+q2][kx] e^{-2pi i r p/10}
 *  stage D: y-finish     F[ky][kx]     = sum_q2 e^{-2pi i ky q2/130} GC[ky%10][q2][kx]
 *           + fused mean|F| (gate) + 24x12 mode extraction.  F never stored. */
__global__ void __launch_bounds__(1024) kfft(int curA){
    extern __shared__ unsigned char s_raw[];
    float*  hs  = (float*)s_raw;            /* 130*132 floats = 68640 B; reused as Z */
    float2* Gb  = (float2*)(hs + 17160);    /* 10140 float2 = 81120 B (GA r=0..5; reused as GC 8580) */
    float2* tws = Gb + 10140;               /* 130 */
    float2* w10 = tws + 130;                /* 100: (cos,sin) of 2pi(rp%10)/10 */
    float*  red = (float*)(w10 + 100);      /* 1024 */
    int bc = blockIdx.x, tid = threadIdx.x;
    const float* hin = curA ? g_hA : g_hB;
    const float* hp = hin + (size_t)bc*HW;
    for(int i=tid;i<HW;i+=1024){ int y=i/130, x=i-y*130; hs[y*132+x]=hp[i]; }
    for(int i=tid;i<130;i+=1024) tws[i]=g_tw[i];
    for(int i=tid;i<100;i+=1024){ int r=i/10,p=i-r*10; w10[i]=g_tw[13*((r*p)%10)]; }
    __syncthreads();

    /* stage A: real input radix-10 along x; store r=0..5 only */
    for(int it=tid; it<1690; it+=1024){
        int y = it/13, q = it-y*13;
        float hv[10];
        #pragma unroll
        for(int p=0;p<10;p++) hv[p]=hs[y*132 + 13*p + q];
        float2* ga = Gb + y*78 + q*6;
        #pragma unroll
        for(int r=0;r<6;r++){
            float ar=0.f, ai=0.f;
            #pragma unroll
            for(int p=0;p<10;p++){
                float2 w = w10[r*10+p];
                ar += hv[p]*w.x;
                ai -= hv[p]*w.y;
            }
            ga[r]=make_float2(ar,ai);
        }
    }
    __syncthreads();

    /* stage B: finish x transform, write Z over the (now dead) h buffer */
    float2* zb = (float2*)hs;   /* [y][kx] : 130*66 */
    for(int it=tid; it<8580; it+=1024){
        int y = it/66, kx = it-y*66;
        int r = kx - (kx/10)*10;
        float sgn = 1.f;
        if(r>5){ r = 10-r; sgn = -1.f; }
        const float2* ga = Gb + y*78 + r;
        float ar=0.f, ai=0.f;
        int id=0;
        #pragma unroll
        for(int q=0;q<13;q++){
            float2 w = tws[id];
            float2 g = ga[q*6];
            float gy = g.y*sgn;
            ar += g.x*w.x + gy*w.y;
            ai += gy*w.x - g.x*w.y;
            id += kx; if(id>=130) id-=130;
        }
        zb[it]=make_float2(ar,ai);
    }
    __syncthreads();

    /* stage C: radix-10 along y (GA dead -> overwrite Gb, needs 8580 <= 10140) */
    for(int it=tid; it<858; it+=1024){
        int q2 = it/66, kx = it-q2*66;
        float2 zp[10];
        #pragma unroll
        for(int p=0;p<10;p++) zp[p]=zb[(13*p+q2)*66 + kx];
        #pragma unroll
        for(int r=0;r<10;r++){
            float ar=0.f, ai=0.f;
            #pragma unroll
            for(int p=0;p<10;p++){
                float2 w = w10[r*10+p];
                ar += zp[p].x*w.x + zp[p].y*w.y;
                ai += zp[p].y*w.x - zp[p].x*w.y;
            }
            Gb[r*858 + it]=make_float2(ar,ai);
        }
    }
    __syncthreads();

    /* stage D: finish y transform; fused gate reduction + mode extraction */
    float lsum=0.f;
    for(int it=tid; it<8580; it+=1024){
        int ky = it/66, kx = it-ky*66;
        int r2 = ky - (ky/10)*10;
        const float2* gc = Gb + r2*858 + kx;
        float ar=0.f, ai=0.f;
        int id=0;
        #pragma unroll
        for(int q=0;q<13;q++){
            float2 w = tws[id];
            float2 g = gc[q*66];
            ar += g.x*w.x + g.y*w.y;
            ai += g.y*w.x - g.x*w.y;
            id += ky; if(id>=130) id-=130;
        }
        lsum += sqrtf(ar*ar+ai*ai);
        if(kx<NM && (ky<NM || ky>=NH-NM)){
            int jr = (ky<NM)? ky : ky-106;
            g_Modes[((size_t)bc*24+jr)*NM+kx]=make_float2(ar,ai);
        }
    }
    red[tid]=lsum; __syncthreads();
    for(int s=512;s>0;s>>=1){ if(tid<s) red[tid]+=red[tid+s]; __syncthreads(); }
    if(tid==0) g_sab[bc]=red[0]/8580.f;
}

/* gate: softmax(sab @ gw + gb) */
__global__ void kgate(const float* __restrict__ gw, const float* __restrict__ gb){
    int b=blockIdx.x, e=threadIdx.x;
    __shared__ float lg[NE];
    if(e<NE){
        float s=gb[e];
        for(int c=0;c<NC;c++) s += g_sab[b*NC+c]*gw[c*NE+e];
        lg[e]=s;
    }
    __syncthreads();
    if(e==0){
        float mx=-1e30f;
        for(int i=0;i<NE;i++) mx=fmaxf(mx,lg[i]);
        float den=0.f;
        for(int i=0;i<NE;i++){ lg[i]=expf(lg[i]-mx); den+=lg[i]; }
        for(int i=0;i<NE;i++) g_gate[b*NE+i]=lg[i]/den;
    }
}

/* M[e] = A[e] @ B[e]  (complex low-rank products, layer weights) */
__global__ void km(const float* __restrict__ A1,const float* __restrict__ B1,
                   const float* __restrict__ A2,const float* __restrict__ B2){
    int e=blockIdx.x, which=blockIdx.y;
    const float* A  = which? A2:A1;
    const float* Bm = which? B2:B1;
    float2* Mo = which? g_M2:g_M1;
    __shared__ float2 as[NC*NR], bs[NR*NC];
    for(int i=threadIdx.x;i<NC*NR;i+=blockDim.x){
        as[i]=make_float2(A [(e*NC*NR+i)*2], A [(e*NC*NR+i)*2+1]);
        bs[i]=make_float2(Bm[(e*NR*NC+i)*2], Bm[(e*NR*NC+i)*2+1]);
    }
    __syncthreads();
    for(int idx=threadIdx.x; idx<NC*NC; idx+=blockDim.x){
        int i=idx/NC, o=idx%NC;
        float rr=0.f, ri=0.f;
        #pragma unroll
        for(int r=0;r<NR;r++){
            float2 a=as[i*NR+r], b2=bs[r*NC+o];
            rr += a.x*b2.x - a.y*b2.y;
            ri += a.x*b2.y + a.y*b2.x;
        }
        Mo[e*NC*NC+idx]=make_float2(rr,ri);
    }
}

/* d[b] = 0.1 * sum_e g[b,e] M[e] */
__global__ void kd(){
    int b=blockIdx.x, which=blockIdx.y;
    const float2* Mm = which? g_M2 : g_M1;
    float2* dd = which? g_d2 : g_d1;
    __shared__ float gs[NE];
    if(threadIdx.x<NE) gs[threadIdx.x]=g_gate[b*NE+threadIdx.x];
    __syncthreads();
    for(int idx=threadIdx.x; idx<NC*NC; idx+=blockDim.x){
        float rr=0.f, ri=0.f;
        #pragma unroll
        for(int e=0;e<NE;e++){
            float2 m=Mm[e*NC*NC+idx];
            rr += gs[e]*m.x; ri += gs[e]*m.y;
        }
        dd[b*NC*NC+idx]=make_float2(0.1f*rr,0.1f*ri);
    }
}

/* mode mixing: o[b,o,p,q] = sum_i ft[b,i,p,q] * (W[i,o,p,q] + d[b,i,o]) */
__global__ void kmix(const float* __restrict__ W1,const float* __restrict__ W2){
    extern __shared__ unsigned char s_raw[];
    float2* tops = (float2*)s_raw;       /* 64*144 */
    float2* ds   = tops + NC*144;        /* 64*8 */
    int ot=blockIdx.x, half=blockIdx.y, b=blockIdx.z;
    const float2* W    = (const float2*)(half? W2:W1);
    const float2* dmat = half? g_d2 : g_d1;
    int jbase = half*NM;
    for(int i=threadIdx.x;i<NC*144;i+=256){
        int c=i/144, pq=i%144;
        tops[i]=g_Modes[(((size_t)b*NC+c)*24 + jbase + pq/NM)*NM + pq%NM];
    }
    for(int i=threadIdx.x;i<NC*8;i+=256){
        int c=i/8, oo=i%8;
        ds[i]=dmat[((size_t)b*NC+c)*NC + ot*8+oo];
    }
    __syncthreads();
    for(int idx=threadIdx.x; idx<8*144; idx+=256){
        int oo=idx/144, pq=idx%144; int o=ot*8+oo;
        float rr=0.f, ri=0.f;
        #pragma unroll 8
        for(int i=0;i<NC;i++){
            float2 t=tops[i*144+pq];
            float2 d=ds[i*8+oo];
            float2 w=W[((size_t)i*NC+o)*144+pq];
            float wr=w.x+d.x, wi=w.y+d.y;
            rr += t.x*wr - t.y*wi;
            ri += t.x*wi + t.y*wr;
        }
        g_OutModes[(((size_t)b*NC+o)*24 + jbase + pq/NM)*NM + pq%NM]=make_float2(rr,ri);
    }
}

/* inverse fft along y (only 24 nonzero bins): Ty[y,q] */
__global__ void kinv1(){
    __shared__ float2 om[24*NM];
    __shared__ float2 tws[NH];
    int bc=blockIdx.x, tid=threadIdx.x;
    for(int i=tid;i<24*NM;i+=blockDim.x) om[i]=g_OutModes[(size_t)bc*24*NM+i];
    for(int i=tid;i<NH;i+=blockDim.x) tws[i]=g_tw[i];
    __syncthreads();
    for(int idx=tid; idx<NH*NM; idx+=blockDim.x){
        int y=idx/NM, q=idx%NM;
        float rr=0.f, ri=0.f;
        #pragma unroll
        for(int j=0;j<24;j++){
            int ky = (j<NM)? j : j+106;
            int t = (ky*y)%NH;
            float2 w=tws[t];
            float2 o=om[j*NM+q];
            rr += o.x*w.x - o.y*w.y;
            ri += o.x*w.y + o.y*w.x;
        }
        g_Ty[(size_t)bc*NH*NM+idx]=make_float2(rr*(1.f/130.f), ri*(1.f/130.f));
    }
}

/* fused: irfft along x (12 bins) + pointwise conv + bias + (gelu) -> new h
 * 4 x-outputs per thread (float4 loads on h). */
__global__ void __launch_bounds__(256) kfinal(int curA, const float* __restrict__ cw,
                       const float* __restrict__ cb, int dogelu){
    extern __shared__ unsigned char s_raw[];
    float*  hs   = (float*)s_raw;           /* 64*132 floats, x padded */
    float*  cws  = hs + NC*132;             /* 4096 */
    float*  cbs  = cws + NC*NC;             /* 64 */
    float2* tys  = (float2*)(cbs + NC);     /* 64*12 */
    float2* twsl = tys + NC*NM;             /* 130 */
    const float* hin  = curA ? g_hA : g_hB;
    float*       hout = curA ? g_hB : g_hA;
    int y=blockIdx.x, b=blockIdx.y, tid=threadIdx.x;
    for(int i=tid;i<NC*NH;i+=256){ int c=i/NH,x=i-c*NH; hs[c*132+x]=hin[(((size_t)b*NC+c)*NH+y)*NH+x]; }
    for(int i=tid;i<NC*2;i+=256){ int c=i>>1; hs[c*132+130+(i&1)]=0.f; }
    for(int i=tid;i<NC*NC;i+=256) cws[i]=cw[i];
    if(tid<NC) cbs[tid]=cb[tid];
    for(int i=tid;i<NC*NM;i+=256){ int c=i/NM,q=i-c*NM; tys[i]=g_Ty[((size_t)(b*NC+c)*NH+y)*NM+q]; }
    for(int i=tid;i<NH;i+=256) twsl[i]=g_tw[i];
    __syncthreads();
    const float4* h4 = (const float4*)hs;
    for(int it=tid; it<NC*33; it+=256){
        int o=it/33, xg=it-o*33;
        int x0=xg*4;
        /* spectral: irfft along x, 12 bins */
        float sac[4];
        float2 t0=tys[o*NM];
        int id[4], xa[4];
        #pragma unroll
        for(int a=0;a<4;a++){ sac[a]=t0.x; id[a]=0; xa[a]=(x0+a<NH)?(x0+a):0; }
        #pragma unroll
        for(int q=1;q<NM;q++){
            float2 t=tys[o*NM+q];
            #pragma unroll
            for(int a=0;a<4;a++){
                id[a]+=xa[a]; if(id[a]>=NH) id[a]-=NH;
                float2 w=twsl[id[a]];
                sac[a] += 2.f*(t.x*w.x - t.y*w.y);
            }
        }
        /* pointwise conv */
        float cac[4];
        float cb0=cbs[o];
        #pragma unroll
        for(int a=0;a<4;a++) cac[a]=cb0;
        #pragma unroll 8
        for(int i=0;i<NC;i++){
            float c = cws[o*NC+i];
            float4 hv = h4[i*33 + xg];
            cac[0]+=c*hv.x; cac[1]+=c*hv.y; cac[2]+=c*hv.z; cac[3]+=c*hv.w;
        }
        float* op = hout + (((size_t)b*NC+o)*NH+y)*NH;
        #pragma unroll
        for(int a=0;a<4;a++){
            int x=x0+a; if(x>=NH) break;
            float v = sac[a]*(1.f/130.f) + cac[a];
            if(dogelu) v = gelu_exact(v);
            op[x]=v;
        }
    }
}

/* head: crop + fc1 + gelu + fc2 (j-tiled x4 with float4 weight broadcast) */
__global__ void __launch_bounds__(128) kout(const float* __restrict__ f1w,
        const float* __restrict__ f1b, const float* __restrict__ f2w,
        const float* __restrict__ f2b, float* __restrict__ out){
    extern __shared__ unsigned char s_raw[];
    float* hs  = (float*)s_raw;     /* 64*128 */
    float* w1s = hs + 8192;         /* 8192 */
    float* b1s = w1s + 8192;        /* 128 */
    float* w2s = b1s + 128;         /* 128 */
    int y=blockIdx.x, b=blockIdx.y, tid=threadIdx.x;
    for(int i=tid;i<8192;i+=128){ int c=i>>7,x=i&127; hs[i]=g_hA[(((size_t)b*NC+c)*NH+y)*NH+x]; }
    for(int i=tid;i<8192;i+=128) w1s[i]=f1w[i];
    if(tid<128){ b1s[tid]=f1b[tid]; w2s[tid]=f2w[tid]; }
    __syncthreads();
    int x=tid;
    float v[NC];
    #pragma unroll
    for(int i=0;i<NC;i++) v[i]=hs[i*128+x];
    const float4* w14 = (const float4*)w1s;
    float acc=f2b[0];
    for(int j=0;j<128;j+=4){
        float s0=b1s[j], s1=b1s[j+1], s2=b1s[j+2], s3=b1s[j+3];
        #pragma unroll
        for(int i=0;i<NC;i++){
            float4 w = w14[(i*128+j)>>2];
            float vi = v[i];
            s0+=vi*w.x; s1+=vi*w.y; s2+=vi*w.z; s3+=vi*w.w;
        }
        acc += gelu_exact(s0)*w2s[j]   + gelu_exact(s1)*w2s[j+1]
             + gelu_exact(s2)*w2s[j+2] + gelu_exact(s3)*w2s[j+3];
    }
    out[((size_t)(b*128+y))*128+x]=acc;
}

/* ------------------------------- host ------------------------------------ */
extern "C" void kernel_launch(void* const* d_in, const int* in_sizes, int n_in,
                              void* d_out, int out_size){
    const float* x    =(const float*)d_in[0];
    const float* grd  =(const float*)d_in[1];
    const float* fc0w =(const float*)d_in[2];
    const float* fc0b =(const float*)d_in[3];
    const float* W1   =(const float*)d_in[4];
    const float* W2   =(const float*)d_in[5];
    const float* A1   =(const float*)d_in[6];
    const float* B1   =(const float*)d_in[7];
    const float* A2   =(const float*)d_in[8];
    const float* B2   =(const float*)d_in[9];
    const float* gw   =(const float*)d_in[10];
    const float* gb   =(const float*)d_in[11];
    const float* cw   =(const float*)d_in[12];
    const float* cb   =(const float*)d_in[13];
    const float* f1w  =(const float*)d_in[14];
    const float* f1b  =(const float*)d_in[15];
    const float* f2w  =(const float*)d_in[16];
    const float* f2b  =(const float*)d_in[17];
    float* out=(float*)d_out;

    const int SMFFT = 17160*4 + 10140*8 + 130*8 + 100*8 + 1024*4;  /* 155696 */
    const int SMMIX = NC*144*8 + NC*8*8;                            /* 77824 */
    const int SMF   = (NC*132 + NC*NC + NC)*4 + (NC*NM + NH)*8;     /* 58128 */
    const int SMO   = (8192+8192+128+128)*4;                        /* 66560 */

    cudaFuncSetAttribute(kfft,   cudaFuncAttributeMaxDynamicSharedMemorySize, SMFFT);
    cudaFuncSetAttribute(kmix,   cudaFuncAttributeMaxDynamicSharedMemorySize, SMMIX);
    cudaFuncSetAttribute(kfinal, cudaFuncAttributeMaxDynamicSharedMemorySize, SMF);
    cudaFuncSetAttribute(kout,   cudaFuncAttributeMaxDynamicSharedMemorySize, SMO);

    ktw<<<1,160>>>();
    k0<<<dim3(NH,NB_),256>>>(x,grd,fc0w,fc0b);

    for(int l=0;l<4;l++){
        int curA = (l%2==0) ? 1 : 0;
        kfft<<<BC,1024,SMFFT>>>(curA);
        kgate<<<NB_,32>>>(gw + (size_t)l*NC*NE, gb + (size_t)l*NE);
        km<<<dim3(NE,2),256>>>(A1+(size_t)l*NE*NC*NR*2, B1+(size_t)l*NE*NR*NC*2,
                               A2+(size_t)l*NE*NC*NR*2, B2+(size_t)l*NE*NR*NC*2);
        kd<<<dim3(NB_,2),256>>>();
        kmix<<<dim3(8,2,NB_),256,SMMIX>>>(W1+(size_t)l*NC*NC*NM*NM*2,
                                          W2+(size_t)l*NC*NC*NM*NM*2);
        kinv1<<<BC,512>>>();
        kfinal<<<dim3(NH,NB_),256,SMF>>>(curA, cw+(size_t)l*NC*NC,
                                         cb+(size_t)l*NC, (l<3)?1:0);
    }
    kout<<<dim3(128,NB_),128,SMO>>>(f1w,f1b,f2w,f2b,out);
}